// round 7
// baseline (speedup 1.0000x reference)
#include <cuda_runtime.h>
#include <math.h>
#include <stdint.h>

// InputLayer: out[b,n,d] = LN_d( (x[b,n]*W[d] + bias[d]) * sqrt(1024) ) * gamma[d] + beta[d]
// Analytic LayerNorm (h affine in a=x[b,n]) -> closed-form stats of (W,b).
// R7: replace per-thread STG.128 with TMA bulk stores (cp.async.bulk), double
// buffered through SMEM. Each block owns 64 contiguous rows (R3's winning
// schedule); tiles of 4 rows = 16KB contiguous bulk stores.

#define SIZE 1024
#define QUADS (SIZE / 4)          // 256 threads per block
#define RPB 64                    // rows per block
#define TILE 4                    // rows per bulk store (16 KB)
#define LN_EPS 1e-5f

__device__ __forceinline__ uint32_t smem_u32(const void* p) {
    uint32_t a;
    asm("{ .reg .u64 t; cvta.to.shared.u64 t, %1; cvt.u32.u64 %0, t; }"
        : "=r"(a) : "l"(p));
    return a;
}

__global__ __launch_bounds__(QUADS, 6)
void il_tma_kernel(const float* __restrict__ x,
                   const float* __restrict__ W,
                   const float* __restrict__ B,
                   const float* __restrict__ G,
                   const float* __restrict__ Be,
                   float* __restrict__ out,
                   int nrows) {
    const float SCALE = 32.0f;                 // sqrt(1024)
    const float S2 = SCALE * SCALE;

    int q = threadIdx.x;                       // 0..255
    int d0 = q * 4;
    int row0 = blockIdx.x * RPB;

    __shared__ float xa[RPB];
    __shared__ float red[5][8];
    __shared__ __align__(16) float buf[2][TILE * SIZE];   // 2 x 16 KB staging

    int cnt = nrows - row0;
    if (cnt > RPB) cnt = RPB;

    if (q < RPB) xa[q] = (q < cnt) ? x[row0 + q] : 0.0f;

    float4 w4  = *(const float4*)(W  + d0);
    float4 b4  = *(const float4*)(B  + d0);
    float4 g4  = *(const float4*)(G  + d0);
    float4 be4 = *(const float4*)(Be + d0);

    // ---- per-block stats reduction over the 1024 (W,b) columns ----
    float s0 = w4.x + w4.y + w4.z + w4.w;
    float s1 = b4.x + b4.y + b4.z + b4.w;
    float s2 = w4.x*w4.x + w4.y*w4.y + w4.z*w4.z + w4.w*w4.w;
    float s3 = b4.x*b4.x + b4.y*b4.y + b4.z*b4.z + b4.w*b4.w;
    float s4 = w4.x*b4.x + w4.y*b4.y + w4.z*b4.z + w4.w*b4.w;

    int lane = q & 31, warp = q >> 5;
    #pragma unroll
    for (int o = 16; o > 0; o >>= 1) {
        s0 += __shfl_down_sync(0xffffffffu, s0, o);
        s1 += __shfl_down_sync(0xffffffffu, s1, o);
        s2 += __shfl_down_sync(0xffffffffu, s2, o);
        s3 += __shfl_down_sync(0xffffffffu, s3, o);
        s4 += __shfl_down_sync(0xffffffffu, s4, o);
    }
    if (lane == 0) {
        red[0][warp] = s0; red[1][warp] = s1; red[2][warp] = s2;
        red[3][warp] = s3; red[4][warp] = s4;
    }
    __syncthreads();

    float t0 = 0.f, t1 = 0.f, t2 = 0.f, t3 = 0.f, t4 = 0.f;
    #pragma unroll
    for (int i = 0; i < 8; i++) {
        t0 += red[0][i]; t1 += red[1][i]; t2 += red[2][i];
        t3 += red[3][i]; t4 += red[4][i];
    }
    const float inv = 1.0f / (float)SIZE;
    float mw = t0 * inv, mb = t1 * inv;
    float vw = fmaf(-mw, mw, t2 * inv);
    float vb = fmaf(-mb, mb, t3 * inv);
    float cv = fmaf(-mw, mb, t4 * inv);

    float4 P, Q;
    P.x = (w4.x - mw) * g4.x;  Q.x = (b4.x - mb) * g4.x;
    P.y = (w4.y - mw) * g4.y;  Q.y = (b4.y - mb) * g4.y;
    P.z = (w4.z - mw) * g4.z;  Q.z = (b4.z - mb) * g4.z;
    P.w = (w4.w - mw) * g4.w;  Q.w = (b4.w - mb) * g4.w;

    // ---- TMA-store pipeline over tiles of 4 rows ----
    int ntiles = cnt / TILE;                   // full tiles (16 full for cnt=64)
    int tail0  = ntiles * TILE;                // leftover rows handled by STG

    uint32_t buf_s[2];
    buf_s[0] = smem_u32(&buf[0][0]);
    buf_s[1] = smem_u32(&buf[1][0]);

    for (int t = 0; t < ntiles; t++) {
        int bi = t & 1;

        if (t >= 2) {
            // buffer bi still owned by bulk-store from tile t-2: wait until
            // its SMEM reads are done, then release to all threads.
            if (q == 0)
                asm volatile("cp.async.bulk.wait_group.read 1;" ::: "memory");
            __syncthreads();
        }

        float4* bb = (float4*)&buf[bi][0];
        #pragma unroll
        for (int j = 0; j < TILE; j++) {
            float a = xa[t * TILE + j];
            float var = S2 * fmaf(a, fmaf(a, vw, 2.0f * cv), vb);
            float tt = SCALE * rsqrtf(var + LN_EPS);
            float c0 = tt * a;

            float4 o;
            o.x = fmaf(c0, P.x, fmaf(tt, Q.x, be4.x));
            o.y = fmaf(c0, P.y, fmaf(tt, Q.y, be4.y));
            o.z = fmaf(c0, P.z, fmaf(tt, Q.z, be4.z));
            o.w = fmaf(c0, P.w, fmaf(tt, Q.w, be4.w));
            bb[j * QUADS + q] = o;
        }
        __syncthreads();

        if (q == 0) {
            asm volatile("fence.proxy.async.shared::cta;" ::: "memory");
            const float* gdst = out + (size_t)(row0 + t * TILE) * SIZE;
            asm volatile(
                "cp.async.bulk.global.shared::cta.bulk_group [%0], [%1], %2;"
                :: "l"(gdst), "r"(buf_s[bi]), "n"(TILE * SIZE * 4)
                : "memory");
            asm volatile("cp.async.bulk.commit_group;" ::: "memory");
        }
    }

    // Tail rows (only when nrows % TILE != 0 in the last block): plain STG.
    for (int r = tail0; r < cnt; r++) {
        float a = xa[r];
        float var = S2 * fmaf(a, fmaf(a, vw, 2.0f * cv), vb);
        float tt = SCALE * rsqrtf(var + LN_EPS);
        float c0 = tt * a;
        float4 o;
        o.x = fmaf(c0, P.x, fmaf(tt, Q.x, be4.x));
        o.y = fmaf(c0, P.y, fmaf(tt, Q.y, be4.y));
        o.z = fmaf(c0, P.z, fmaf(tt, Q.z, be4.z));
        o.w = fmaf(c0, P.w, fmaf(tt, Q.w, be4.w));
        __stcs((float4*)(out + (size_t)(row0 + r) * SIZE + d0), o);
    }

    // Ensure all bulk stores are globally visible before kernel completion.
    if (q == 0)
        asm volatile("cp.async.bulk.wait_group 0;" ::: "memory");
}

extern "C" void kernel_launch(void* const* d_in, const int* in_sizes, int n_in,
                              void* d_out, int out_size) {
    const float* x  = (const float*)d_in[0];   // (2048, 32)
    const float* W  = (const float*)d_in[1];   // (1024, 1)
    const float* B  = (const float*)d_in[2];   // (1024,)
    const float* G  = (const float*)d_in[3];   // (1024,)
    const float* Be = (const float*)d_in[4];   // (1024,)
    float* out = (float*)d_out;

    int nrows = in_sizes[0];                   // 65536 rows

    int grid = (nrows + RPB - 1) / RPB;        // 1024 blocks (R3 schedule)
    il_tma_kernel<<<grid, QUADS>>>(x, W, B, G, Be, out, nrows);
}

// round 8
// speedup vs baseline: 1.1235x; 1.1235x over previous
#include <cuda_runtime.h>
#include <math.h>

// InputLayer: out[b,n,d] = LN_d( (x[b,n]*W[d] + bias[d]) * sqrt(1024) ) * gamma[d] + beta[d]
// Analytic LayerNorm (h affine in a=x[b,n]) -> closed-form mean/var from per-
// column stats of (W, bias). Single fused kernel, R3 schedule (grid=1024,
// 64 rows/block, 256 threads). Per-row scalars (t, c0) precomputed into smem;
// hot loop is LDS.64 + 8 FMA + STG.128 -> pure store-bandwidth bound.

#define SIZE 1024
#define QUADS (SIZE / 4)          // 256 threads per block
#define RPB 64                    // rows per block
#define LN_EPS 1e-5f

__global__ __launch_bounds__(QUADS)
void il_fused_kernel(const float* __restrict__ x,
                     const float* __restrict__ W,
                     const float* __restrict__ B,
                     const float* __restrict__ G,
                     const float* __restrict__ Be,
                     float* __restrict__ out,
                     int nrows) {
    const float SCALE = 32.0f;                 // sqrt(1024)
    const float S2 = SCALE * SCALE;

    int q = threadIdx.x;                       // 0..255
    int d0 = q * 4;
    int row0 = blockIdx.x * RPB;

    __shared__ float2 tc[RPB];                 // per-row (t, c0 = t*a)
    __shared__ float red[5][8];                // 5 stats x 8 warps

    float4 w4  = *(const float4*)(W  + d0);
    float4 b4  = *(const float4*)(B  + d0);
    float4 g4  = *(const float4*)(G  + d0);
    float4 be4 = *(const float4*)(Be + d0);

    // ---- per-block stats reduction over the 1024 (W,b) columns ----
    float s0 = w4.x + w4.y + w4.z + w4.w;                              // sum W
    float s1 = b4.x + b4.y + b4.z + b4.w;                              // sum B
    float s2 = w4.x*w4.x + w4.y*w4.y + w4.z*w4.z + w4.w*w4.w;          // sum W^2
    float s3 = b4.x*b4.x + b4.y*b4.y + b4.z*b4.z + b4.w*b4.w;          // sum B^2
    float s4 = w4.x*b4.x + w4.y*b4.y + w4.z*b4.z + w4.w*b4.w;          // sum W*B

    int lane = q & 31, warp = q >> 5;
    #pragma unroll
    for (int o = 16; o > 0; o >>= 1) {
        s0 += __shfl_down_sync(0xffffffffu, s0, o);
        s1 += __shfl_down_sync(0xffffffffu, s1, o);
        s2 += __shfl_down_sync(0xffffffffu, s2, o);
        s3 += __shfl_down_sync(0xffffffffu, s3, o);
        s4 += __shfl_down_sync(0xffffffffu, s4, o);
    }
    if (lane == 0) {
        red[0][warp] = s0; red[1][warp] = s1; red[2][warp] = s2;
        red[3][warp] = s3; red[4][warp] = s4;
    }
    __syncthreads();

    float t0 = 0.f, t1 = 0.f, t2 = 0.f, t3 = 0.f, t4 = 0.f;
    #pragma unroll
    for (int i = 0; i < 8; i++) {
        t0 += red[0][i]; t1 += red[1][i]; t2 += red[2][i];
        t3 += red[3][i]; t4 += red[4][i];
    }
    const float inv = 1.0f / (float)SIZE;
    float mw = t0 * inv, mb = t1 * inv;
    float vw = fmaf(-mw, mw, t2 * inv);        // Var(W)
    float vb = fmaf(-mb, mb, t3 * inv);        // Var(B)
    float cv = fmaf(-mw, mb, t4 * inv);        // Cov(W,B)

    // Per-row scalars: t = S * rsqrt(var+eps), c0 = t * a  (64 threads, once)
    if (q < RPB) {
        int r = row0 + q;
        float a = (r < nrows) ? x[r] : 0.0f;
        float var = S2 * fmaf(a, fmaf(a, vw, 2.0f * cv), vb);
        float t = SCALE * rsqrtf(var + LN_EPS);
        tc[q] = make_float2(t, t * a);
    }

    // P = (W - meanW) * gamma ;  Q = (B - meanB) * gamma
    float4 P, Q;
    P.x = (w4.x - mw) * g4.x;  Q.x = (b4.x - mb) * g4.x;
    P.y = (w4.y - mw) * g4.y;  Q.y = (b4.y - mb) * g4.y;
    P.z = (w4.z - mw) * g4.z;  Q.z = (b4.z - mb) * g4.z;
    P.w = (w4.w - mw) * g4.w;  Q.w = (b4.w - mb) * g4.w;

    __syncthreads();

    int rmax = nrows - row0;
    if (rmax > RPB) rmax = RPB;

    float4* obase = (float4*)(out + (size_t)row0 * SIZE + d0);

    #pragma unroll 4
    for (int r = 0; r < rmax; r++) {
        float2 s = tc[r];                      // (t, c0)

        float4 o;
        o.x = fmaf(s.y, P.x, fmaf(s.x, Q.x, be4.x));
        o.y = fmaf(s.y, P.y, fmaf(s.x, Q.y, be4.y));
        o.z = fmaf(s.y, P.z, fmaf(s.x, Q.z, be4.z));
        o.w = fmaf(s.y, P.w, fmaf(s.x, Q.w, be4.w));

        __stcs(obase + (size_t)r * QUADS, o);  // streaming: never re-read
    }
}

extern "C" void kernel_launch(void* const* d_in, const int* in_sizes, int n_in,
                              void* d_out, int out_size) {
    const float* x  = (const float*)d_in[0];   // (2048, 32)
    const float* W  = (const float*)d_in[1];   // (1024, 1)
    const float* B  = (const float*)d_in[2];   // (1024,)
    const float* G  = (const float*)d_in[3];   // (1024,)
    const float* Be = (const float*)d_in[4];   // (1024,)
    float* out = (float*)d_out;

    int nrows = in_sizes[0];                   // 65536 rows

    int grid = (nrows + RPB - 1) / RPB;        // 1024 blocks (R3 schedule)
    il_fused_kernel<<<grid, QUADS>>>(x, W, B, G, Be, out, nrows);
}